// round 1
// baseline (speedup 1.0000x reference)
#include <cuda_runtime.h>
#include <cuda_bf16.h>
#include <math.h>

// Problem constants: B=16, C=256, H=W=64, k=7
#define BATCH 16
#define CH 256
#define HW 64
#define PLANE (HW*HW)          // 4096
#define KW 7
#define KK (KW*KW)             // 49
#define RED 64                 // C/4
#define PAD 3
#define TILE 70                // 64 + 2*3

// ---------------- scratch (no allocation allowed) ----------------
__device__ float g_pooled[BATCH * CH];                 // [B,C]
__device__ float g_h[BATCH * RED];                     // [B,64]
__device__ float g_fused[BATCH * CH * KK];             // [B,C,49]
__device__ float g_tmp[(size_t)BATCH * CH * PLANE];    // 64 MB depthwise output

// ---------------- 1) global average pool ----------------
__global__ void pool_kernel(const float* __restrict__ x) {
    int bc = blockIdx.x;                       // b*C + c
    const float4* p4 = (const float4*)(x + (size_t)bc * PLANE);
    float s = 0.f;
    #pragma unroll
    for (int i = 0; i < 4; ++i) {
        float4 v = p4[threadIdx.x + i * 256];
        s += v.x + v.y + v.z + v.w;
    }
    __shared__ float red[8];
    #pragma unroll
    for (int o = 16; o; o >>= 1) s += __shfl_xor_sync(0xffffffffu, s, o);
    if ((threadIdx.x & 31) == 0) red[threadIdx.x >> 5] = s;
    __syncthreads();
    if (threadIdx.x < 32) {
        float v = (threadIdx.x < 8) ? red[threadIdx.x] : 0.f;
        #pragma unroll
        for (int o = 4; o; o >>= 1) v += __shfl_xor_sync(0xffffffffu, v, o);
        if (threadIdx.x == 0) g_pooled[bc] = v * (1.f / (float)PLANE);
    }
}

// ---------------- 2) MLP stage 1: h = gelu(pooled @ w1^T + b1) ----------------
__global__ void mlp_kernel(const float* __restrict__ w1, const float* __restrict__ b1) {
    __shared__ float ps[BATCH * CH];           // 16 KB
    int t = threadIdx.x;                       // 1024 threads
    #pragma unroll
    for (int i = 0; i < 4; ++i) ps[t + i * 1024] = g_pooled[t + i * 1024];
    __syncthreads();
    int b = t >> 6;                            // /64
    int r = t & 63;
    const float* wrow = w1 + r * CH;
    const float* prow = ps + b * CH;
    float acc = b1[r];
    #pragma unroll 8
    for (int c = 0; c < CH; ++c) acc += prow[c] * wrow[c];
    // exact gelu
    float g = 0.5f * acc * (1.0f + erff(acc * 0.70710678118654752f));
    g_h[b * RED + r] = g;
}

// ---------------- 3) fused dynamic weights: dw + (h @ w2^T + b2) ----------------
__global__ void fused_kernel(const float* __restrict__ dw,
                             const float* __restrict__ w2,
                             const float* __restrict__ b2) {
    int bc = blockIdx.x;                       // b*C + c
    int b = bc >> 8;
    int c = bc & 255;
    __shared__ float hs[RED];
    if (threadIdx.x < RED) hs[threadIdx.x] = g_h[b * RED + threadIdx.x];
    __syncthreads();
    int i = threadIdx.x;
    if (i < KK) {
        int j = c * KK + i;                    // row of w2
        const float* wrow = w2 + (size_t)j * RED;
        float acc = dw[j] + b2[j];
        #pragma unroll
        for (int r = 0; r < RED; ++r) acc += hs[r] * wrow[r];
        g_fused[(size_t)bc * KK + i] = acc;
    }
}

// ---------------- 4) depthwise 7x7, per-(b,c) kernel ----------------
__global__ void dwconv_kernel(const float* __restrict__ x) {
    int bc = blockIdx.x;
    const float* in = x + (size_t)bc * PLANE;
    __shared__ float s_in[TILE * TILE];        // 19600 B
    __shared__ float s_w[KK];
    if (threadIdx.x < KK) s_w[threadIdx.x] = g_fused[(size_t)bc * KK + threadIdx.x];
    // load 70x70 tile with zero padding
    for (int idx = threadIdx.x; idx < TILE * TILE; idx += 256) {
        int r = idx / TILE, cc = idx % TILE;
        int gy = r - PAD, gx = cc - PAD;
        float v = 0.f;
        if ((unsigned)gy < HW && (unsigned)gx < HW) v = in[gy * HW + gx];
        s_in[idx] = v;
    }
    __syncthreads();
    float* out = g_tmp + (size_t)bc * PLANE;
    #pragma unroll
    for (int j = 0; j < 16; ++j) {
        int idx = threadIdx.x + j * 256;
        int row = idx >> 6;
        int col = idx & 63;
        const float* base = s_in + row * TILE + col;
        float acc = 0.f;
        #pragma unroll
        for (int ky = 0; ky < KW; ++ky) {
            #pragma unroll
            for (int kx = 0; kx < KW; ++kx)
                acc += s_w[ky * KW + kx] * base[ky * TILE + kx];
        }
        out[idx] = acc;
    }
}

// ---------------- 5) pointwise 1x1: out[b,o,p] = sum_c tmp[b,c,p]*pw[o,c] ----------------
#define PW_BM 64
#define PW_BN 64
#define PW_BK 16
#define PW_LD 68
__global__ void pw_kernel(const float* __restrict__ pw, float* __restrict__ out) {
    __shared__ __align__(16) float As[PW_BK][PW_LD];   // As[c][o]
    __shared__ __align__(16) float Bs[PW_BK][PW_LD];   // Bs[c][p]
    int b  = blockIdx.z;
    int o0 = blockIdx.y * PW_BM;
    int p0 = blockIdx.x * PW_BN;
    const float* tb = g_tmp + (size_t)b * CH * PLANE;
    float* ob = out + (size_t)b * CH * PLANE;
    int t = threadIdx.x;
    int tx = t & 15, ty = t >> 4;
    float acc[4][4] = {};
    for (int c0 = 0; c0 < CH; c0 += PW_BK) {
        #pragma unroll
        for (int i = 0; i < 4; ++i) {
            int idx = t + i * 256;             // 0..1023 over 64x16 tile
            int o_l = idx >> 4, c_l = idx & 15;
            As[c_l][o_l] = pw[(o0 + o_l) * CH + c0 + c_l];
        }
        #pragma unroll
        for (int i = 0; i < 4; ++i) {
            int idx = t + i * 256;             // 0..1023 over 16x64 tile
            int c_l = idx >> 6, p_l = idx & 63;
            Bs[c_l][p_l] = tb[(size_t)(c0 + c_l) * PLANE + p0 + p_l];
        }
        __syncthreads();
        #pragma unroll
        for (int kk = 0; kk < PW_BK; ++kk) {
            float4 ra = *(const float4*)&As[kk][ty * 4];
            float4 rb = *(const float4*)&Bs[kk][tx * 4];
            float a0[4] = {ra.x, ra.y, ra.z, ra.w};
            float b0[4] = {rb.x, rb.y, rb.z, rb.w};
            #pragma unroll
            for (int i = 0; i < 4; ++i)
                #pragma unroll
                for (int j = 0; j < 4; ++j)
                    acc[i][j] += a0[i] * b0[j];
        }
        __syncthreads();
    }
    #pragma unroll
    for (int i = 0; i < 4; ++i) {
        float4 v = make_float4(acc[i][0], acc[i][1], acc[i][2], acc[i][3]);
        *(float4*)&ob[(size_t)(o0 + ty * 4 + i) * PLANE + p0 + tx * 4] = v;
    }
}

// ---------------- launch ----------------
extern "C" void kernel_launch(void* const* d_in, const int* in_sizes, int n_in,
                              void* d_out, int out_size) {
    const float* x  = (const float*)d_in[0];
    const float* dw = (const float*)d_in[1];
    const float* pw = (const float*)d_in[2];
    const float* w1 = (const float*)d_in[3];
    const float* b1 = (const float*)d_in[4];
    const float* w2 = (const float*)d_in[5];
    const float* b2 = (const float*)d_in[6];
    float* out = (float*)d_out;

    pool_kernel<<<BATCH * CH, 256>>>(x);
    mlp_kernel<<<1, 1024>>>(w1, b1);
    fused_kernel<<<BATCH * CH, 64>>>(dw, w2, b2);
    dwconv_kernel<<<BATCH * CH, 256>>>(x);
    pw_kernel<<<dim3(PLANE / PW_BN, CH / PW_BM, BATCH), 256>>>(pw, out);
}

// round 4
// speedup vs baseline: 1.5053x; 1.5053x over previous
#include <cuda_runtime.h>
#include <cuda_bf16.h>
#include <math.h>
#include <cstdint>

// Problem constants: B=16, C=256, H=W=64, k=7
#define BATCH 16
#define CH 256
#define HW 64
#define PLANE (HW*HW)          // 4096
#define KW 7
#define KK (KW*KW)             // 49
#define RED 64                 // C/4
#define PAD 3
#define TILE 70
#define TSTR 72

// ---------------- scratch (no allocation allowed) ----------------
__device__ float g_pooled[BATCH * CH];
__device__ float g_h[BATCH * RED];
__device__ float g_fused[BATCH * CH * KK];
__device__ __nv_bfloat16 g_whi[CH * CH];                        // weight hi [o][c]
__device__ __nv_bfloat16 g_wlo[CH * CH];                        // weight lo [o][c]
__device__ __nv_bfloat16 g_bhi[(size_t)BATCH * CH * PLANE];     // dw out hi [b][c][p] 32MB
__device__ __nv_bfloat16 g_blo[(size_t)BATCH * CH * PLANE];     // dw out lo [b][c][p] 32MB

// ---------------- PTX helpers (sm_100 BASELINE only) ----------------
__device__ __forceinline__ uint32_t smem_u32(const void* p) {
    uint32_t a;
    asm("{ .reg .u64 t; cvta.to.shared.u64 t, %1; cvt.u32.u64 %0, t; }" : "=r"(a) : "l"(p));
    return a;
}
__device__ __forceinline__ void cp_async16(uint32_t dst, const void* src) {
    asm volatile("cp.async.cg.shared.global [%0], [%1], 16;" :: "r"(dst), "l"(src));
}
#define CP_COMMIT() asm volatile("cp.async.commit_group;" ::: "memory")
#define CP_WAIT(n)  asm volatile("cp.async.wait_group %0;" :: "n"(n) : "memory")

__device__ __forceinline__ void ldsm_x4(uint32_t& r0, uint32_t& r1, uint32_t& r2, uint32_t& r3,
                                        uint32_t addr) {
    asm volatile("ldmatrix.sync.aligned.m8n8.x4.shared.b16 {%0,%1,%2,%3}, [%4];"
        : "=r"(r0), "=r"(r1), "=r"(r2), "=r"(r3) : "r"(addr));
}
__device__ __forceinline__ void ldsm_x4t(uint32_t& r0, uint32_t& r1, uint32_t& r2, uint32_t& r3,
                                         uint32_t addr) {
    asm volatile("ldmatrix.sync.aligned.m8n8.x4.trans.shared.b16 {%0,%1,%2,%3}, [%4];"
        : "=r"(r0), "=r"(r1), "=r"(r2), "=r"(r3) : "r"(addr));
}
__device__ __forceinline__ void mma16816(float* d, const uint32_t* a, const uint32_t* b) {
    asm volatile(
        "mma.sync.aligned.m16n8k16.row.col.f32.bf16.bf16.f32 "
        "{%0,%1,%2,%3}, {%4,%5,%6,%7}, {%8,%9}, {%0,%1,%2,%3};"
        : "+f"(d[0]), "+f"(d[1]), "+f"(d[2]), "+f"(d[3])
        : "r"(a[0]), "r"(a[1]), "r"(a[2]), "r"(a[3]), "r"(b[0]), "r"(b[1]));
}

// ---------------- 1) global average pool ----------------
__global__ void pool_kernel(const float* __restrict__ x) {
    int bc = blockIdx.x;
    const float4* p4 = (const float4*)(x + (size_t)bc * PLANE);
    float s = 0.f;
    #pragma unroll
    for (int i = 0; i < 4; ++i) {
        float4 v = p4[threadIdx.x + i * 256];
        s += v.x + v.y + v.z + v.w;
    }
    __shared__ float red[8];
    #pragma unroll
    for (int o = 16; o; o >>= 1) s += __shfl_xor_sync(0xffffffffu, s, o);
    if ((threadIdx.x & 31) == 0) red[threadIdx.x >> 5] = s;
    __syncthreads();
    if (threadIdx.x < 32) {
        float v = (threadIdx.x < 8) ? red[threadIdx.x] : 0.f;
        #pragma unroll
        for (int o = 4; o; o >>= 1) v += __shfl_xor_sync(0xffffffffu, v, o);
        if (threadIdx.x == 0) g_pooled[bc] = v * (1.f / (float)PLANE);
    }
}

// ---------------- 2) MLP: h = gelu(pooled @ w1^T + b1) ----------------
__global__ void mlp_kernel(const float* __restrict__ w1, const float* __restrict__ b1) {
    __shared__ float ps[BATCH * CH];
    int t = threadIdx.x;
    #pragma unroll
    for (int i = 0; i < 4; ++i) ps[t + i * 1024] = g_pooled[t + i * 1024];
    __syncthreads();
    int b = t >> 6, r = t & 63;
    const float* wrow = w1 + r * CH;
    const float* prow = ps + b * CH;
    float acc = b1[r];
    #pragma unroll 8
    for (int c = 0; c < CH; ++c) acc += prow[c] * wrow[c];
    g_h[b * RED + r] = 0.5f * acc * (1.0f + erff(acc * 0.70710678118654752f));
}

// ---------------- 3) fused dynamic weights ----------------
__global__ void fused_kernel(const float* __restrict__ dw,
                             const float* __restrict__ w2,
                             const float* __restrict__ b2) {
    int bc = blockIdx.x;
    int b = bc >> 8, c = bc & 255;
    __shared__ float hs[RED];
    if (threadIdx.x < RED) hs[threadIdx.x] = g_h[b * RED + threadIdx.x];
    __syncthreads();
    int i = threadIdx.x;
    if (i < KK) {
        int j = c * KK + i;
        const float* wrow = w2 + (size_t)j * RED;
        float acc = dw[j] + b2[j];
        #pragma unroll
        for (int r = 0; r < RED; ++r) acc += hs[r] * wrow[r];
        g_fused[(size_t)bc * KK + i] = acc;
    }
}

// ---------------- 4) depthwise 7x7 -> bf16 hi/lo split output ----------------
__global__ void dwconv_kernel(const float* __restrict__ x) {
    int bc = blockIdx.x;
    const float* in = x + (size_t)bc * PLANE;
    __shared__ float s_in[TILE * TSTR];
    __shared__ float s_w[KK];
    if (threadIdx.x < KK) s_w[threadIdx.x] = g_fused[(size_t)bc * KK + threadIdx.x];
    for (int idx = threadIdx.x; idx < TILE * TILE; idx += 256) {
        int r = idx / TILE, cc = idx % TILE;
        int gy = r - PAD, gx = cc - PAD;
        float v = 0.f;
        if ((unsigned)gy < HW && (unsigned)gx < HW) v = in[gy * HW + gx];
        s_in[r * TSTR + cc] = v;
    }
    __syncthreads();
    __nv_bfloat16* ohi = g_bhi + (size_t)bc * PLANE;
    __nv_bfloat16* olo = g_blo + (size_t)bc * PLANE;
    #pragma unroll
    for (int g = 0; g < 4; ++g) {
        int q = threadIdx.x + g * 256;
        int row = q >> 4;
        int colq = (q & 15) * 4;
        const float* base = s_in + row * TSTR + colq;
        float acc[4] = {0.f, 0.f, 0.f, 0.f};
        #pragma unroll
        for (int ky = 0; ky < KW; ++ky) {
            const float* rp = base + ky * TSTR;
            float4 a = *(const float4*)(rp);
            float4 bq = *(const float4*)(rp + 4);
            float4 cq = *(const float4*)(rp + 8);
            float v[12] = {a.x, a.y, a.z, a.w, bq.x, bq.y, bq.z, bq.w, cq.x, cq.y, cq.z, cq.w};
            #pragma unroll
            for (int kx = 0; kx < KW; ++kx) {
                float w = s_w[ky * KW + kx];
                acc[0] += w * v[kx + 0];
                acc[1] += w * v[kx + 1];
                acc[2] += w * v[kx + 2];
                acc[3] += w * v[kx + 3];
            }
        }
        __nv_bfloat162 h01 = __floats2bfloat162_rn(acc[0], acc[1]);
        __nv_bfloat162 h23 = __floats2bfloat162_rn(acc[2], acc[3]);
        float l0 = acc[0] - __bfloat162float(__low2bfloat16(h01));
        float l1 = acc[1] - __bfloat162float(__high2bfloat16(h01));
        float l2 = acc[2] - __bfloat162float(__low2bfloat16(h23));
        float l3 = acc[3] - __bfloat162float(__high2bfloat16(h23));
        __nv_bfloat162 lo01 = __floats2bfloat162_rn(l0, l1);
        __nv_bfloat162 lo23 = __floats2bfloat162_rn(l2, l3);
        int o = row * HW + colq;
        *(uint2*)&ohi[o] = make_uint2(*(uint32_t*)&h01, *(uint32_t*)&h23);
        *(uint2*)&olo[o] = make_uint2(*(uint32_t*)&lo01, *(uint32_t*)&lo23);
    }
}

// ---------------- 5a) weight bf16 hi/lo split ----------------
__global__ void wprep_kernel(const float* __restrict__ pw) {
    int idx = blockIdx.x * 256 + threadIdx.x;
    float v = pw[idx];
    __nv_bfloat16 h = __float2bfloat16(v);
    g_whi[idx] = h;
    g_wlo[idx] = __float2bfloat16(v - __bfloat162float(h));
}

// ---------------- 5b) mma.sync bf16 GEMM: out[b,o,p] = sum_c W[o,c]*Bm[b,c,p] ----------------
// Block tile M=128(o) x N=128(p); K chunks of 32; 3 passes (WhXh, WhXl, WlXh) in fp32 accum.
// 8 warps: 2 (m) x 4 (n); warp tile 64x32; mma m16n8k16.
#define NCHUNK 8
#define KC 32
#define SA_STR 40                           // bf16 elems per A smem row (32 + 8 pad)
#define SB_STR 136                          // bf16 elems per B smem row (128 + 8 pad)
#define SA_SZ (128 * SA_STR * 2)            // 10240 B per dtype
#define SB_SZ (KC * SB_STR * 2)             // 8704 B per dtype
#define OFF_AH 0
#define OFF_AL (SA_SZ)
#define OFF_BH (2 * SA_SZ)
#define OFF_BL (2 * SA_SZ + SB_SZ)
#define STAGE (2 * SA_SZ + 2 * SB_SZ)       // 37888 B
#define GEMM_SMEM (2 * STAGE)               // 75776 B

__global__ void __launch_bounds__(256, 1) pw_mma_kernel(float* __restrict__ out) {
    extern __shared__ char smem[];
    uint32_t sbase = smem_u32(smem);
    int t = threadIdx.x;
    int lane = t & 31, wid = t >> 5;
    int wm = wid & 1, wn = wid >> 1;        // warp 64x32 tile at (wm*64, wn*32)

    int bB = blockIdx.z;
    int o0 = blockIdx.y * 128;
    int p0 = blockIdx.x * 128;

    const __nv_bfloat16* whi = g_whi;
    const __nv_bfloat16* wlo = g_wlo;
    const __nv_bfloat16* bhi = g_bhi;
    const __nv_bfloat16* blo = g_blo;

    // stage loader: A rows [o0..o0+128) cols [c0..c0+32); B rows c, cols [p0..p0+128)
    auto load_stage = [&](int stg, int cidx) {
        int c0 = cidx * KC;
        uint32_t sb = sbase + stg * STAGE;
        #pragma unroll
        for (int it = 0; it < 2; ++it) {
            int id = it * 256 + t;          // 0..511
            int r = id >> 2, cc = id & 3;   // A: 128 rows x 4 x 16B
            uint32_t dst = sb + OFF_AH + (uint32_t)(r * SA_STR + cc * 8) * 2;
            const __nv_bfloat16* sh = whi + (o0 + r) * CH + c0 + cc * 8;
            cp_async16(dst, sh);
            cp_async16(dst + (OFF_AL - OFF_AH), wlo + (o0 + r) * CH + c0 + cc * 8);
        }
        #pragma unroll
        for (int it = 0; it < 2; ++it) {
            int id = it * 256 + t;
            int r = id >> 4, cc = id & 15;  // B: 32 rows x 16 x 16B
            size_t src = ((size_t)(bB * CH + c0 + r)) * PLANE + p0 + cc * 8;
            uint32_t dst = sb + OFF_BH + (uint32_t)(r * SB_STR + cc * 8) * 2;
            cp_async16(dst, bhi + src);
            cp_async16(dst + (OFF_BL - OFF_BH), blo + src);
        }
    };

    float acc[4][4][4];
    #pragma unroll
    for (int i = 0; i < 4; ++i)
        #pragma unroll
        for (int j = 0; j < 4; ++j)
            #pragma unroll
            for (int r = 0; r < 4; ++r) acc[i][j][r] = 0.f;

    load_stage(0, 0); CP_COMMIT();
    load_stage(1, 1); CP_COMMIT();

    for (int cidx = 0; cidx < NCHUNK; ++cidx) {
        if (cidx == NCHUNK - 1) { CP_WAIT(0); } else { CP_WAIT(1); }
        __syncthreads();

        uint32_t sb = sbase + (cidx & 1) * STAGE;
        #pragma unroll
        for (int ks = 0; ks < 2; ++ks) {
            uint32_t aH[4][4], aL[4][4];
            #pragma unroll
            for (int i = 0; i < 4; ++i) {
                uint32_t addr = sb + OFF_AH +
                    (uint32_t)((wm * 64 + i * 16 + (lane & 15)) * SA_STR + ks * 16 + (lane >> 4) * 8) * 2;
                ldsm_x4(aH[i][0], aH[i][1], aH[i][2], aH[i][3], addr);
                ldsm_x4(aL[i][0], aL[i][1], aL[i][2], aL[i][3], addr + (OFF_AL - OFF_AH));
            }
            uint32_t bH[4][2], bL[4][2];
            #pragma unroll
            for (int j2 = 0; j2 < 2; ++j2) {
                uint32_t addr = sb + OFF_BH +
                    (uint32_t)((ks * 16 + (lane & 15)) * SB_STR + wn * 32 + j2 * 16 + (lane >> 4) * 8) * 2;
                uint32_t r0, r1, r2, r3;
                ldsm_x4t(r0, r1, r2, r3, addr);
                bH[j2 * 2][0] = r0; bH[j2 * 2][1] = r1;
                bH[j2 * 2 + 1][0] = r2; bH[j2 * 2 + 1][1] = r3;
                ldsm_x4t(r0, r1, r2, r3, addr + (OFF_BL - OFF_BH));
                bL[j2 * 2][0] = r0; bL[j2 * 2][1] = r1;
                bL[j2 * 2 + 1][0] = r2; bL[j2 * 2 + 1][1] = r3;
            }
            #pragma unroll
            for (int i = 0; i < 4; ++i)
                #pragma unroll
                for (int j = 0; j < 4; ++j) {
                    mma16816(acc[i][j], aH[i], bH[j]);
                    mma16816(acc[i][j], aH[i], bL[j]);
                    mma16816(acc[i][j], aL[i], bH[j]);
                }
        }
        __syncthreads();
        if (cidx + 2 < NCHUNK) { load_stage(cidx & 1, cidx + 2); CP_COMMIT(); }
    }

    // epilogue: D frag (m16n8): c0,c1 -> (row=g, col=tig*2+{0,1}); c2,c3 -> row=g+8
    int g = lane >> 2, tig = lane & 3;
    #pragma unroll
    for (int i = 0; i < 4; ++i) {
        int o = o0 + wm * 64 + i * 16 + g;
        float* orow = out + ((size_t)(bB * CH + o)) * PLANE;
        #pragma unroll
        for (int j = 0; j < 4; ++j) {
            int p = p0 + wn * 32 + j * 8 + tig * 2;
            *(float2*)&orow[p] = make_float2(acc[i][j][0], acc[i][j][1]);
            *(float2*)&orow[p + 8 * PLANE] = make_float2(acc[i][j][2], acc[i][j][3]);
        }
    }
}

// ---------------- launch ----------------
extern "C" void kernel_launch(void* const* d_in, const int* in_sizes, int n_in,
                              void* d_out, int out_size) {
    const float* x  = (const float*)d_in[0];
    const float* dw = (const float*)d_in[1];
    const float* pw = (const float*)d_in[2];
    const float* w1 = (const float*)d_in[3];
    const float* b1 = (const float*)d_in[4];
    const float* w2 = (const float*)d_in[5];
    const float* b2 = (const float*)d_in[6];
    float* out = (float*)d_out;

    cudaFuncSetAttribute(pw_mma_kernel, cudaFuncAttributeMaxDynamicSharedMemorySize, GEMM_SMEM);

    pool_kernel<<<BATCH * CH, 256>>>(x);
    mlp_kernel<<<1, 1024>>>(w1, b1);
    wprep_kernel<<<CH * CH / 256, 256>>>(pw);
    fused_kernel<<<BATCH * CH, 64>>>(dw, w2, b2);
    dwconv_kernel<<<BATCH * CH, 256>>>(x);
    pw_mma_kernel<<<dim3(PLANE / 128, CH / 128, BATCH), 256, GEMM_SMEM>>>(out);
}

// round 5
// speedup vs baseline: 1.5733x; 1.0452x over previous
#include <cuda_runtime.h>
#include <cuda_bf16.h>
#include <math.h>
#include <cstdint>

// Problem constants: B=16, C=256, H=W=64, k=7
#define BATCH 16
#define CH 256
#define HW 64
#define PLANE (HW*HW)          // 4096
#define KW 7
#define KK (KW*KW)             // 49
#define RED 64                 // C/4
#define PAD 3
#define TILE 70
#define TSTR 72

// ---------------- scratch (no allocation allowed) ----------------
__device__ float g_pooled[BATCH * CH];
__device__ float g_h[BATCH * RED];
__device__ float g_fused[BATCH * CH * KK];
__device__ __nv_bfloat16 g_whi[CH * CH];                        // weight hi [o][c]
__device__ __nv_bfloat16 g_wlo[CH * CH];                        // weight lo [o][c]
__device__ __nv_bfloat16 g_bhi[(size_t)BATCH * CH * PLANE];     // dw out hi [b][c][p] 32MB
__device__ __nv_bfloat16 g_blo[(size_t)BATCH * CH * PLANE];     // dw out lo [b][c][p] 32MB

// ---------------- PTX helpers (sm_100 BASELINE only) ----------------
__device__ __forceinline__ uint32_t smem_u32(const void* p) {
    uint32_t a;
    asm("{ .reg .u64 t; cvta.to.shared.u64 t, %1; cvt.u32.u64 %0, t; }" : "=r"(a) : "l"(p));
    return a;
}
__device__ __forceinline__ void cp_async16(uint32_t dst, const void* src) {
    asm volatile("cp.async.cg.shared.global [%0], [%1], 16;" :: "r"(dst), "l"(src));
}
#define CP_COMMIT() asm volatile("cp.async.commit_group;" ::: "memory")
#define CP_WAIT(n)  asm volatile("cp.async.wait_group %0;" :: "n"(n) : "memory")

__device__ __forceinline__ void ldsm_x4(uint32_t& r0, uint32_t& r1, uint32_t& r2, uint32_t& r3,
                                        uint32_t addr) {
    asm volatile("ldmatrix.sync.aligned.m8n8.x4.shared.b16 {%0,%1,%2,%3}, [%4];"
        : "=r"(r0), "=r"(r1), "=r"(r2), "=r"(r3) : "r"(addr));
}
__device__ __forceinline__ void ldsm_x4t(uint32_t& r0, uint32_t& r1, uint32_t& r2, uint32_t& r3,
                                         uint32_t addr) {
    asm volatile("ldmatrix.sync.aligned.m8n8.x4.trans.shared.b16 {%0,%1,%2,%3}, [%4];"
        : "=r"(r0), "=r"(r1), "=r"(r2), "=r"(r3) : "r"(addr));
}
__device__ __forceinline__ void mma16816(float* d, const uint32_t* a, const uint32_t* b) {
    asm volatile(
        "mma.sync.aligned.m16n8k16.row.col.f32.bf16.bf16.f32 "
        "{%0,%1,%2,%3}, {%4,%5,%6,%7}, {%8,%9}, {%0,%1,%2,%3};"
        : "+f"(d[0]), "+f"(d[1]), "+f"(d[2]), "+f"(d[3])
        : "r"(a[0]), "r"(a[1]), "r"(a[2]), "r"(a[3]), "r"(b[0]), "r"(b[1]));
}

// packed f32x2 (PTX ISA 8.6, baseline sm_100)
__device__ __forceinline__ uint64_t pack2(float lo, float hi) {
    uint64_t r;
    asm("mov.b64 %0, {%1, %2};" : "=l"(r) : "f"(lo), "f"(hi));
    return r;
}
__device__ __forceinline__ void fma2(uint64_t& acc, uint64_t a, uint64_t b) {
    asm("fma.rn.f32x2 %0, %1, %2, %0;" : "+l"(acc) : "l"(a), "l"(b));
}
__device__ __forceinline__ float2 unpack2(uint64_t v) {
    float2 f;
    asm("mov.b64 {%0, %1}, %2;" : "=f"(f.x), "=f"(f.y) : "l"(v));
    return f;
}

// ---------------- 1) global average pool ----------------
__global__ void pool_kernel(const float* __restrict__ x) {
    int bc = blockIdx.x;
    const float4* p4 = (const float4*)(x + (size_t)bc * PLANE);
    float s = 0.f;
    #pragma unroll
    for (int i = 0; i < 4; ++i) {
        float4 v = p4[threadIdx.x + i * 256];
        s += v.x + v.y + v.z + v.w;
    }
    __shared__ float red[8];
    #pragma unroll
    for (int o = 16; o; o >>= 1) s += __shfl_xor_sync(0xffffffffu, s, o);
    if ((threadIdx.x & 31) == 0) red[threadIdx.x >> 5] = s;
    __syncthreads();
    if (threadIdx.x < 32) {
        float v = (threadIdx.x < 8) ? red[threadIdx.x] : 0.f;
        #pragma unroll
        for (int o = 4; o; o >>= 1) v += __shfl_xor_sync(0xffffffffu, v, o);
        if (threadIdx.x == 0) g_pooled[bc] = v * (1.f / (float)PLANE);
    }
}

// ---------------- 2) MLP: h = gelu(pooled @ w1^T + b1) ----------------
__global__ void mlp_kernel(const float* __restrict__ w1, const float* __restrict__ b1) {
    __shared__ float ps[BATCH * CH];
    int t = threadIdx.x;
    #pragma unroll
    for (int i = 0; i < 4; ++i) ps[t + i * 1024] = g_pooled[t + i * 1024];
    __syncthreads();
    int b = t >> 6, r = t & 63;
    const float* wrow = w1 + r * CH;
    const float* prow = ps + b * CH;
    float acc = b1[r];
    #pragma unroll 8
    for (int c = 0; c < CH; ++c) acc += prow[c] * wrow[c];
    g_h[b * RED + r] = 0.5f * acc * (1.0f + erff(acc * 0.70710678118654752f));
}

// ---------------- 3) fused dynamic weights (one block per channel) ----------------
__global__ void fused_kernel(const float* __restrict__ dw,
                             const float* __restrict__ w2,
                             const float* __restrict__ b2) {
    int c = blockIdx.x;                         // 0..255
    __shared__ float w2s[KK * RED];             // 3136 floats (12.5 KB)
    __shared__ float hs[BATCH * 65];            // padded stride 65
    int t = threadIdx.x;                        // 256
    const float* wsrc = w2 + (size_t)c * KK * RED;
    for (int k = t; k < KK * RED; k += 256) w2s[k] = wsrc[k];
    for (int k = t; k < BATCH * RED; k += 256) hs[(k >> 6) * 65 + (k & 63)] = g_h[k];
    __syncthreads();
    #pragma unroll
    for (int it = 0; it < 4; ++it) {
        int idx = it * 256 + t;                 // idx = i*16 + b
        if (idx < KK * BATCH) {
            int i = idx >> 4, b = idx & 15;
            int j = c * KK + i;
            float acc = dw[j] + b2[j];
            const float* wr = w2s + i * RED;
            const float* hr = hs + b * 65;
            #pragma unroll 16
            for (int r = 0; r < RED; ++r) acc += hr[r] * wr[r];
            g_fused[((size_t)(b * CH + c)) * KK + i] = acc;
        }
    }
}

// ---------------- 4) depthwise 7x7, packed f32x2, 8 outputs/thread ----------------
__global__ void dwconv_kernel(const float* __restrict__ x) {
    int bc = blockIdx.x;
    const float* in = x + (size_t)bc * PLANE;
    __shared__ float s_in[TILE * TSTR];         // rows 16B-aligned (72*4=288)
    __shared__ uint64_t s_wp[KK];               // duplicated weight pairs
    if (threadIdx.x < KK) {
        float w = g_fused[(size_t)bc * KK + threadIdx.x];
        s_wp[threadIdx.x] = pack2(w, w);
    }
    for (int idx = threadIdx.x; idx < TILE * TILE; idx += 256) {
        int r = idx / TILE, cc = idx % TILE;
        int gy = r - PAD, gx = cc - PAD;
        float v = 0.f;
        if ((unsigned)gy < HW && (unsigned)gx < HW) v = in[gy * HW + gx];
        s_in[r * TSTR + cc] = v;
    }
    __syncthreads();
    __nv_bfloat16* ohi = g_bhi + (size_t)bc * PLANE;
    __nv_bfloat16* olo = g_blo + (size_t)bc * PLANE;
    #pragma unroll
    for (int g = 0; g < 2; ++g) {
        int q = threadIdx.x + g * 256;          // 0..511
        int row = q >> 3;                       // 64 rows
        int colo = (q & 7) * 8;                 // 8-wide output group
        const float* base = s_in + row * TSTR + colo;
        uint64_t acc[4];
        #pragma unroll
        for (int j = 0; j < 4; ++j) acc[j] = pack2(0.f, 0.f);
        #pragma unroll
        for (int ky = 0; ky < KW; ++ky) {
            const float* rp = base + ky * TSTR;
            float4 va = *(const float4*)(rp);
            float4 vb = *(const float4*)(rp + 4);
            float4 vc = *(const float4*)(rp + 8);
            float4 vd = *(const float4*)(rp + 12);
            float v[14] = {va.x, va.y, va.z, va.w, vb.x, vb.y, vb.z, vb.w,
                           vc.x, vc.y, vc.z, vc.w, vd.x, vd.y};
            uint64_t p[13];
            #pragma unroll
            for (int k = 0; k < 13; ++k) p[k] = pack2(v[k], v[k + 1]);
            #pragma unroll
            for (int kx = 0; kx < KW; ++kx) {
                uint64_t wp = s_wp[ky * KW + kx];
                fma2(acc[0], wp, p[kx + 0]);
                fma2(acc[1], wp, p[kx + 2]);
                fma2(acc[2], wp, p[kx + 4]);
                fma2(acc[3], wp, p[kx + 6]);
            }
        }
        // hi/lo bf16 split, 8 outputs
        uint32_t hi[4], lo[4];
        #pragma unroll
        for (int j = 0; j < 4; ++j) {
            float2 a = unpack2(acc[j]);
            __nv_bfloat162 h = __floats2bfloat162_rn(a.x, a.y);
            float lx = a.x - __bfloat162float(__low2bfloat16(h));
            float ly = a.y - __bfloat162float(__high2bfloat16(h));
            __nv_bfloat162 l = __floats2bfloat162_rn(lx, ly);
            hi[j] = *(uint32_t*)&h;
            lo[j] = *(uint32_t*)&l;
        }
        int o = row * HW + colo;
        *(uint4*)&ohi[o] = make_uint4(hi[0], hi[1], hi[2], hi[3]);
        *(uint4*)&olo[o] = make_uint4(lo[0], lo[1], lo[2], lo[3]);
    }
}

// ---------------- 5a) weight bf16 hi/lo split ----------------
__global__ void wprep_kernel(const float* __restrict__ pw) {
    int idx = blockIdx.x * 256 + threadIdx.x;
    float v = pw[idx];
    __nv_bfloat16 h = __float2bfloat16(v);
    g_whi[idx] = h;
    g_wlo[idx] = __float2bfloat16(v - __bfloat162float(h));
}

// ---------------- 5b) mma.sync bf16 GEMM, 3-stage cp.async pipeline ----------------
#define NCHUNK 8
#define KC 32
#define SA_STR 40
#define SB_STR 136
#define SA_SZ (128 * SA_STR * 2)
#define SB_SZ (KC * SB_STR * 2)
#define OFF_AH 0
#define OFF_AL (SA_SZ)
#define OFF_BH (2 * SA_SZ)
#define OFF_BL (2 * SA_SZ + SB_SZ)
#define STAGE (2 * SA_SZ + 2 * SB_SZ)       // 37888 B
#define NSTAGE 3
#define GEMM_SMEM (NSTAGE * STAGE)          // 113664 B

__global__ void __launch_bounds__(256, 1) pw_mma_kernel(float* __restrict__ out) {
    extern __shared__ char smem[];
    uint32_t sbase = smem_u32(smem);
    int t = threadIdx.x;
    int lane = t & 31, wid = t >> 5;
    int wm = wid & 1, wn = wid >> 1;

    int bB = blockIdx.z;
    int o0 = blockIdx.y * 128;
    int p0 = blockIdx.x * 128;

    const __nv_bfloat16* whi = g_whi;
    const __nv_bfloat16* wlo = g_wlo;
    const __nv_bfloat16* bhi = g_bhi;
    const __nv_bfloat16* blo = g_blo;

    auto load_stage = [&](int stg, int cidx) {
        int c0 = cidx * KC;
        uint32_t sb = sbase + stg * STAGE;
        #pragma unroll
        for (int it = 0; it < 2; ++it) {
            int id = it * 256 + t;
            int r = id >> 2, cc = id & 3;
            uint32_t dst = sb + OFF_AH + (uint32_t)(r * SA_STR + cc * 8) * 2;
            cp_async16(dst, whi + (o0 + r) * CH + c0 + cc * 8);
            cp_async16(dst + (OFF_AL - OFF_AH), wlo + (o0 + r) * CH + c0 + cc * 8);
        }
        #pragma unroll
        for (int it = 0; it < 2; ++it) {
            int id = it * 256 + t;
            int r = id >> 4, cc = id & 15;
            size_t src = ((size_t)(bB * CH + c0 + r)) * PLANE + p0 + cc * 8;
            uint32_t dst = sb + OFF_BH + (uint32_t)(r * SB_STR + cc * 8) * 2;
            cp_async16(dst, bhi + src);
            cp_async16(dst + (OFF_BL - OFF_BH), blo + src);
        }
    };

    float acc[4][4][4];
    #pragma unroll
    for (int i = 0; i < 4; ++i)
        #pragma unroll
        for (int j = 0; j < 4; ++j)
            #pragma unroll
            for (int r = 0; r < 4; ++r) acc[i][j][r] = 0.f;

    load_stage(0, 0); CP_COMMIT();
    load_stage(1, 1); CP_COMMIT();
    load_stage(2, 2); CP_COMMIT();

    for (int cidx = 0; cidx < NCHUNK; ++cidx) {
        CP_WAIT(2);
        __syncthreads();

        uint32_t sb = sbase + (cidx % NSTAGE) * STAGE;
        #pragma unroll
        for (int ks = 0; ks < 2; ++ks) {
            uint32_t aH[4][4], aL[4][4];
            #pragma unroll
            for (int i = 0; i < 4; ++i) {
                uint32_t addr = sb + OFF_AH +
                    (uint32_t)((wm * 64 + i * 16 + (lane & 15)) * SA_STR + ks * 16 + (lane >> 4) * 8) * 2;
                ldsm_x4(aH[i][0], aH[i][1], aH[i][2], aH[i][3], addr);
                ldsm_x4(aL[i][0], aL[i][1], aL[i][2], aL[i][3], addr + (OFF_AL - OFF_AH));
            }
            uint32_t bH[4][2], bL[4][2];
            #pragma unroll
            for (int j2 = 0; j2 < 2; ++j2) {
                uint32_t addr = sb + OFF_BH +
                    (uint32_t)((ks * 16 + (lane & 15)) * SB_STR + wn * 32 + j2 * 16 + (lane >> 4) * 8) * 2;
                uint32_t r0, r1, r2, r3;
                ldsm_x4t(r0, r1, r2, r3, addr);
                bH[j2 * 2][0] = r0; bH[j2 * 2][1] = r1;
                bH[j2 * 2 + 1][0] = r2; bH[j2 * 2 + 1][1] = r3;
                ldsm_x4t(r0, r1, r2, r3, addr + (OFF_BL - OFF_BH));
                bL[j2 * 2][0] = r0; bL[j2 * 2][1] = r1;
                bL[j2 * 2 + 1][0] = r2; bL[j2 * 2 + 1][1] = r3;
            }
            #pragma unroll
            for (int i = 0; i < 4; ++i)
                #pragma unroll
                for (int j = 0; j < 4; ++j) {
                    mma16816(acc[i][j], aH[i], bH[j]);
                    mma16816(acc[i][j], aH[i], bL[j]);
                    mma16816(acc[i][j], aL[i], bH[j]);
                }
        }
        __syncthreads();
        if (cidx + NSTAGE < NCHUNK) {
            load_stage((cidx + NSTAGE) % NSTAGE, cidx + NSTAGE);
        }
        CP_COMMIT();   // always commit (possibly empty) to keep wait_group ledger valid
    }

    int g = lane >> 2, tig = lane & 3;
    #pragma unroll
    for (int i = 0; i < 4; ++i) {
        int o = o0 + wm * 64 + i * 16 + g;
        float* orow = out + ((size_t)(bB * CH + o)) * PLANE;
        #pragma unroll
        for (int j = 0; j < 4; ++j) {
            int p = p0 + wn * 32 + j * 8 + tig * 2;
            *(float2*)&orow[p] = make_float2(acc[i][j][0], acc[i][j][1]);
            *(float2*)&orow[p + 8 * PLANE] = make_float2(acc[i][j][2], acc[i][j][3]);
        }
    }
}

// ---------------- launch ----------------
extern "C" void kernel_launch(void* const* d_in, const int* in_sizes, int n_in,
                              void* d_out, int out_size) {
    const float* x  = (const float*)d_in[0];
    const float* dw = (const float*)d_in[1];
    const float* pw = (const float*)d_in[2];
    const float* w1 = (const float*)d_in[3];
    const float* b1 = (const float*)d_in[4];
    const float* w2 = (const float*)d_in[5];
    const float* b2 = (const float*)d_in[6];
    float* out = (float*)d_out;

    cudaFuncSetAttribute(pw_mma_kernel, cudaFuncAttributeMaxDynamicSharedMemorySize, GEMM_SMEM);

    pool_kernel<<<BATCH * CH, 256>>>(x);
    mlp_kernel<<<1, 1024>>>(w1, b1);
    wprep_kernel<<<CH * CH / 256, 256>>>(pw);
    fused_kernel<<<CH, 256>>>(dw, w2, b2);
    dwconv_kernel<<<BATCH * CH, 256>>>(x);
    pw_mma_kernel<<<dim3(PLANE / 128, CH / 128, BATCH), 256, GEMM_SMEM>>>(out);
}

// round 6
// speedup vs baseline: 1.6169x; 1.0277x over previous
#include <cuda_runtime.h>
#include <cuda_bf16.h>
#include <math.h>
#include <cstdint>

// Problem constants: B=16, C=256, H=W=64, k=7
#define BATCH 16
#define CH 256
#define HW 64
#define PLANE (HW*HW)          // 4096
#define KW 7
#define KK (KW*KW)             // 49
#define RED 64                 // C/4
#define PAD 3
#define TILE 70
#define TSTR 72

// ---------------- scratch (no allocation allowed) ----------------
__device__ float g_pooled[BATCH * CH];
__device__ float g_h[BATCH * RED];
__device__ float g_fused[BATCH * CH * KK];
__device__ __nv_bfloat16 g_whi[CH * CH];                        // weight hi [o][c]
__device__ __nv_bfloat16 g_wlo[CH * CH];                        // weight lo [o][c]
__device__ __nv_bfloat16 g_bhi[(size_t)BATCH * CH * PLANE];     // dw out hi [b][c][p] 32MB
__device__ __nv_bfloat16 g_blo[(size_t)BATCH * CH * PLANE];     // dw out lo [b][c][p] 32MB

// ---------------- PTX helpers (sm_100 BASELINE only) ----------------
__device__ __forceinline__ uint32_t smem_u32(const void* p) {
    uint32_t a;
    asm("{ .reg .u64 t; cvta.to.shared.u64 t, %1; cvt.u32.u64 %0, t; }" : "=r"(a) : "l"(p));
    return a;
}
__device__ __forceinline__ void cp_async16(uint32_t dst, const void* src) {
    asm volatile("cp.async.cg.shared.global [%0], [%1], 16;" :: "r"(dst), "l"(src));
}
#define CP_COMMIT() asm volatile("cp.async.commit_group;" ::: "memory")
#define CP_WAIT(n)  asm volatile("cp.async.wait_group %0;" :: "n"(n) : "memory")

__device__ __forceinline__ void ldsm_x4(uint32_t& r0, uint32_t& r1, uint32_t& r2, uint32_t& r3,
                                        uint32_t addr) {
    asm volatile("ldmatrix.sync.aligned.m8n8.x4.shared.b16 {%0,%1,%2,%3}, [%4];"
        : "=r"(r0), "=r"(r1), "=r"(r2), "=r"(r3) : "r"(addr));
}
__device__ __forceinline__ void ldsm_x4t(uint32_t& r0, uint32_t& r1, uint32_t& r2, uint32_t& r3,
                                         uint32_t addr) {
    asm volatile("ldmatrix.sync.aligned.m8n8.x4.trans.shared.b16 {%0,%1,%2,%3}, [%4];"
        : "=r"(r0), "=r"(r1), "=r"(r2), "=r"(r3) : "r"(addr));
}
__device__ __forceinline__ void mma16816(float* d, const uint32_t* a, const uint32_t* b) {
    asm volatile(
        "mma.sync.aligned.m16n8k16.row.col.f32.bf16.bf16.f32 "
        "{%0,%1,%2,%3}, {%4,%5,%6,%7}, {%8,%9}, {%0,%1,%2,%3};"
        : "+f"(d[0]), "+f"(d[1]), "+f"(d[2]), "+f"(d[3])
        : "r"(a[0]), "r"(a[1]), "r"(a[2]), "r"(a[3]), "r"(b[0]), "r"(b[1]));
}

// ---------------- 1) global average pool ----------------
__global__ void pool_kernel(const float* __restrict__ x) {
    int bc = blockIdx.x;
    const float4* p4 = (const float4*)(x + (size_t)bc * PLANE);
    float s = 0.f;
    #pragma unroll
    for (int i = 0; i < 4; ++i) {
        float4 v = p4[threadIdx.x + i * 256];
        s += v.x + v.y + v.z + v.w;
    }
    __shared__ float red[8];
    #pragma unroll
    for (int o = 16; o; o >>= 1) s += __shfl_xor_sync(0xffffffffu, s, o);
    if ((threadIdx.x & 31) == 0) red[threadIdx.x >> 5] = s;
    __syncthreads();
    if (threadIdx.x < 32) {
        float v = (threadIdx.x < 8) ? red[threadIdx.x] : 0.f;
        #pragma unroll
        for (int o = 4; o; o >>= 1) v += __shfl_xor_sync(0xffffffffu, v, o);
        if (threadIdx.x == 0) g_pooled[bc] = v * (1.f / (float)PLANE);
    }
}

// ---------------- 2) MLP: h = gelu(pooled @ w1^T + b1) ----------------
__global__ void mlp_kernel(const float* __restrict__ w1, const float* __restrict__ b1) {
    __shared__ float ps[BATCH * CH];
    int t = threadIdx.x;
    #pragma unroll
    for (int i = 0; i < 4; ++i) ps[t + i * 1024] = g_pooled[t + i * 1024];
    __syncthreads();
    int b = t >> 6, r = t & 63;
    const float* wrow = w1 + r * CH;
    const float* prow = ps + b * CH;
    float acc = b1[r];
    #pragma unroll 8
    for (int c = 0; c < CH; ++c) acc += prow[c] * wrow[c];
    g_h[b * RED + r] = 0.5f * acc * (1.0f + erff(acc * 0.70710678118654752f));
}

// ---------------- 3) fused dynamic weights (one block per channel) ----------------
__global__ void fused_kernel(const float* __restrict__ dw,
                             const float* __restrict__ w2,
                             const float* __restrict__ b2) {
    int c = blockIdx.x;                         // 0..255
    __shared__ float w2s[KK * RED];             // 12.5 KB
    __shared__ float hs[BATCH * 65];            // padded stride 65
    int t = threadIdx.x;                        // 256
    const float* wsrc = w2 + (size_t)c * KK * RED;
    for (int k = t; k < KK * RED; k += 256) w2s[k] = wsrc[k];
    for (int k = t; k < BATCH * RED; k += 256) hs[(k >> 6) * 65 + (k & 63)] = g_h[k];
    __syncthreads();
    #pragma unroll
    for (int it = 0; it < 4; ++it) {
        int idx = it * 256 + t;                 // idx = i*16 + b
        if (idx < KK * BATCH) {
            int i = idx >> 4, b = idx & 15;
            int j = c * KK + i;
            float acc = dw[j] + b2[j];
            const float* wr = w2s + i * RED;
            const float* hr = hs + b * 65;
            #pragma unroll 16
            for (int r = 0; r < RED; ++r) acc += hr[r] * wr[r];
            g_fused[((size_t)(b * CH + c)) * KK + i] = acc;
        }
    }
}

// ---------------- 4) depthwise 7x7, 8 outputs/thread, scalar FFMA ----------------
__global__ void dwconv_kernel(const float* __restrict__ x) {
    int bc = blockIdx.x;
    const float* in = x + (size_t)bc * PLANE;
    __shared__ float s_in[TILE * TSTR];
    __shared__ float s_w[KK];
    if (threadIdx.x < KK) s_w[threadIdx.x] = g_fused[(size_t)bc * KK + threadIdx.x];
    for (int idx = threadIdx.x; idx < TILE * TILE; idx += 256) {
        int r = idx / TILE, cc = idx % TILE;
        int gy = r - PAD, gx = cc - PAD;
        float v = 0.f;
        if ((unsigned)gy < HW && (unsigned)gx < HW) v = in[gy * HW + gx];
        s_in[r * TSTR + cc] = v;
    }
    __syncthreads();
    __nv_bfloat16* ohi = g_bhi + (size_t)bc * PLANE;
    __nv_bfloat16* olo = g_blo + (size_t)bc * PLANE;
    #pragma unroll
    for (int g = 0; g < 2; ++g) {
        int q = threadIdx.x + g * 256;          // 0..511
        int row = q >> 3;                       // 64 rows
        int colo = (q & 7) * 8;                 // 8-wide output group
        const float* base = s_in + row * TSTR + colo;
        float acc[8] = {0.f, 0.f, 0.f, 0.f, 0.f, 0.f, 0.f, 0.f};
        #pragma unroll
        for (int ky = 0; ky < KW; ++ky) {
            const float* rp = base + ky * TSTR;
            float4 va = *(const float4*)(rp);
            float4 vb = *(const float4*)(rp + 4);
            float4 vc = *(const float4*)(rp + 8);
            float4 vd = *(const float4*)(rp + 12);
            float v[14] = {va.x, va.y, va.z, va.w, vb.x, vb.y, vb.z, vb.w,
                           vc.x, vc.y, vc.z, vc.w, vd.x, vd.y};
            #pragma unroll
            for (int kx = 0; kx < KW; ++kx) {
                float w = s_w[ky * KW + kx];
                #pragma unroll
                for (int j = 0; j < 8; ++j) acc[j] += w * v[kx + j];
            }
        }
        uint32_t hi[4], lo[4];
        #pragma unroll
        for (int j = 0; j < 4; ++j) {
            __nv_bfloat162 h = __floats2bfloat162_rn(acc[2 * j], acc[2 * j + 1]);
            float lx = acc[2 * j]     - __bfloat162float(__low2bfloat16(h));
            float ly = acc[2 * j + 1] - __bfloat162float(__high2bfloat16(h));
            __nv_bfloat162 l = __floats2bfloat162_rn(lx, ly);
            hi[j] = *(uint32_t*)&h;
            lo[j] = *(uint32_t*)&l;
        }
        int o = row * HW + colo;
        *(uint4*)&ohi[o] = make_uint4(hi[0], hi[1], hi[2], hi[3]);
        *(uint4*)&olo[o] = make_uint4(lo[0], lo[1], lo[2], lo[3]);
    }
}

// ---------------- 5a) weight bf16 hi/lo split ----------------
__global__ void wprep_kernel(const float* __restrict__ pw) {
    int idx = blockIdx.x * 256 + threadIdx.x;
    float v = pw[idx];
    __nv_bfloat16 h = __float2bfloat16(v);
    g_whi[idx] = h;
    g_wlo[idx] = __float2bfloat16(v - __bfloat162float(h));
}

// ---------------- 5b) mma.sync bf16 GEMM (R4-proven 2-stage pipeline) ----------------
#define NCHUNK 8
#define KC 32
#define SA_STR 40
#define SB_STR 136
#define SA_SZ (128 * SA_STR * 2)
#define SB_SZ (KC * SB_STR * 2)
#define OFF_AH 0
#define OFF_AL (SA_SZ)
#define OFF_BH (2 * SA_SZ)
#define OFF_BL (2 * SA_SZ + SB_SZ)
#define STAGE (2 * SA_SZ + 2 * SB_SZ)       // 37888 B
#define GEMM_SMEM (2 * STAGE)               // 75776 B

__global__ void __launch_bounds__(256, 1) pw_mma_kernel(float* __restrict__ out) {
    extern __shared__ char smem[];
    uint32_t sbase = smem_u32(smem);
    int t = threadIdx.x;
    int lane = t & 31, wid = t >> 5;
    int wm = wid & 1, wn = wid >> 1;

    int bB = blockIdx.z;
    int o0 = blockIdx.y * 128;
    int p0 = blockIdx.x * 128;

    const __nv_bfloat16* whi = g_whi;
    const __nv_bfloat16* wlo = g_wlo;
    const __nv_bfloat16* bhi = g_bhi;
    const __nv_bfloat16* blo = g_blo;

    auto load_stage = [&](int stg, int cidx) {
        int c0 = cidx * KC;
        uint32_t sb = sbase + stg * STAGE;
        #pragma unroll
        for (int it = 0; it < 2; ++it) {
            int id = it * 256 + t;
            int r = id >> 2, cc = id & 3;
            uint32_t dst = sb + OFF_AH + (uint32_t)(r * SA_STR + cc * 8) * 2;
            cp_async16(dst, whi + (o0 + r) * CH + c0 + cc * 8);
            cp_async16(dst + (OFF_AL - OFF_AH), wlo + (o0 + r) * CH + c0 + cc * 8);
        }
        #pragma unroll
        for (int it = 0; it < 2; ++it) {
            int id = it * 256 + t;
            int r = id >> 4, cc = id & 15;
            size_t src = ((size_t)(bB * CH + c0 + r)) * PLANE + p0 + cc * 8;
            uint32_t dst = sb + OFF_BH + (uint32_t)(r * SB_STR + cc * 8) * 2;
            cp_async16(dst, bhi + src);
            cp_async16(dst + (OFF_BL - OFF_BH), blo + src);
        }
    };

    float acc[4][4][4];
    #pragma unroll
    for (int i = 0; i < 4; ++i)
        #pragma unroll
        for (int j = 0; j < 4; ++j)
            #pragma unroll
            for (int r = 0; r < 4; ++r) acc[i][j][r] = 0.f;

    load_stage(0, 0); CP_COMMIT();
    load_stage(1, 1); CP_COMMIT();

    for (int cidx = 0; cidx < NCHUNK; ++cidx) {
        if (cidx == NCHUNK - 1) { CP_WAIT(0); } else { CP_WAIT(1); }
        __syncthreads();

        uint32_t sb = sbase + (cidx & 1) * STAGE;
        #pragma unroll
        for (int ks = 0; ks < 2; ++ks) {
            uint32_t aH[4][4], aL[4][4];
            #pragma unroll
            for (int i = 0; i < 4; ++i) {
                uint32_t addr = sb + OFF_AH +
                    (uint32_t)((wm * 64 + i * 16 + (lane & 15)) * SA_STR + ks * 16 + (lane >> 4) * 8) * 2;
                ldsm_x4(aH[i][0], aH[i][1], aH[i][2], aH[i][3], addr);
                ldsm_x4(aL[i][0], aL[i][1], aL[i][2], aL[i][3], addr + (OFF_AL - OFF_AH));
            }
            uint32_t bH[4][2], bL[4][2];
            #pragma unroll
            for (int j2 = 0; j2 < 2; ++j2) {
                uint32_t addr = sb + OFF_BH +
                    (uint32_t)((ks * 16 + (lane & 15)) * SB_STR + wn * 32 + j2 * 16 + (lane >> 4) * 8) * 2;
                uint32_t r0, r1, r2, r3;
                ldsm_x4t(r0, r1, r2, r3, addr);
                bH[j2 * 2][0] = r0; bH[j2 * 2][1] = r1;
                bH[j2 * 2 + 1][0] = r2; bH[j2 * 2 + 1][1] = r3;
                ldsm_x4t(r0, r1, r2, r3, addr + (OFF_BL - OFF_BH));
                bL[j2 * 2][0] = r0; bL[j2 * 2][1] = r1;
                bL[j2 * 2 + 1][0] = r2; bL[j2 * 2 + 1][1] = r3;
            }
            #pragma unroll
            for (int i = 0; i < 4; ++i)
                #pragma unroll
                for (int j = 0; j < 4; ++j) {
                    mma16816(acc[i][j], aH[i], bH[j]);
                    mma16816(acc[i][j], aH[i], bL[j]);
                    mma16816(acc[i][j], aL[i], bH[j]);
                }
        }
        __syncthreads();
        if (cidx + 2 < NCHUNK) { load_stage(cidx & 1, cidx + 2); CP_COMMIT(); }
    }

    int g = lane >> 2, tig = lane & 3;
    #pragma unroll
    for (int i = 0; i < 4; ++i) {
        int o = o0 + wm * 64 + i * 16 + g;
        float* orow = out + ((size_t)(bB * CH + o)) * PLANE;
        #pragma unroll
        for (int j = 0; j < 4; ++j) {
            int p = p0 + wn * 32 + j * 8 + tig * 2;
            *(float2*)&orow[p] = make_float2(acc[i][j][0], acc[i][j][1]);
            *(float2*)&orow[p + 8 * PLANE] = make_float2(acc[i][j][2], acc[i][j][3]);
        }
    }
}

// ---------------- launch ----------------
extern "C" void kernel_launch(void* const* d_in, const int* in_sizes, int n_in,
                              void* d_out, int out_size) {
    const float* x  = (const float*)d_in[0];
    const float* dw = (const float*)d_in[1];
    const float* pw = (const float*)d_in[2];
    const float* w1 = (const float*)d_in[3];
    const float* b1 = (const float*)d_in[4];
    const float* w2 = (const float*)d_in[5];
    const float* b2 = (const float*)d_in[6];
    float* out = (float*)d_out;

    cudaFuncSetAttribute(pw_mma_kernel, cudaFuncAttributeMaxDynamicSharedMemorySize, GEMM_SMEM);

    pool_kernel<<<BATCH * CH, 256>>>(x);
    mlp_kernel<<<1, 1024>>>(w1, b1);
    wprep_kernel<<<CH * CH / 256, 256>>>(pw);
    fused_kernel<<<CH, 256>>>(dw, w2, b2);
    dwconv_kernel<<<BATCH * CH, 256>>>(x);
    pw_mma_kernel<<<dim3(PLANE / 128, CH / 128, BATCH), 256, GEMM_SMEM>>>(out);
}